// round 4
// baseline (speedup 1.0000x reference)
#include <cuda_runtime.h>

#define NN   50000
#define EE   1600000
#define DIN  128
#define DOUT 64

// Scratch (static device globals: allocation-free, allowed).
// __align__(16): float4 / red.v4 access paths require 16B alignment.
__device__ __align__(16) float g_x[3][NN * DOUT];     // (h @ W_i) * rsqrt(deg_out_i)
__device__ __align__(16) float g_agg[3][NN * DOUT];   // segment_sum accumulators
__device__ __align__(16) float g_deg[6][NN];          // [2h]=deg_out(h), [2h+1]=deg_in(h)

// ---------------------------------------------------------------------------
// Degree counts: one pass over all 3 edge lists
// ---------------------------------------------------------------------------
__global__ void deg_kernel(const int* __restrict__ s0, const int* __restrict__ d0,
                           const int* __restrict__ s1, const int* __restrict__ d1,
                           const int* __restrict__ s2, const int* __restrict__ d2) {
    int i = blockIdx.x * blockDim.x + threadIdx.x;
    if (i >= EE) return;
    atomicAdd(&g_deg[0][s0[i]], 1.0f);
    atomicAdd(&g_deg[1][d0[i]], 1.0f);
    atomicAdd(&g_deg[2][s1[i]], 1.0f);
    atomicAdd(&g_deg[3][d1[i]], 1.0f);
    atomicAdd(&g_deg[4][s2[i]], 1.0f);
    atomicAdd(&g_deg[5][d2[i]], 1.0f);
}

// ---------------------------------------------------------------------------
// x_h = (h @ W_h) * rsqrt(max(deg_out_h, 1))
// Block: 256 threads, 64 rows x 64 cols tile, 4x4 register tile per thread.
// K tiled by 32 (W tile 8KB smem), H tile 64x130 (padded, 33.3KB smem).
// ---------------------------------------------------------------------------
__global__ void gemm_kernel(const float* __restrict__ h,
                            const float* __restrict__ W0,
                            const float* __restrict__ W1,
                            const float* __restrict__ W2) {
    const int head = blockIdx.y;
    const float* W = (head == 0) ? W0 : (head == 1) ? W1 : W2;

    __shared__ float Hs[64][130];      // padded stride: 4-row step hits distinct banks
    __shared__ float Ws[32 * DOUT];    // one K-tile of W

    const int t = threadIdx.x;
    const int rowbase = blockIdx.x * 64;

    // Load H tile (64 rows x 128 cols), zero-padded past N
    #pragma unroll
    for (int j = 0; j < 8; j++) {
        int idx = t + j * 256;         // 0..2047 float4 slots
        int r   = idx >> 5;            // 0..63
        int kq  = idx & 31;            // float4 column
        int row = rowbase + r;
        float4 v = make_float4(0.f, 0.f, 0.f, 0.f);
        if (row < NN) v = ((const float4*)(h + (size_t)row * DIN))[kq];
        Hs[r][kq * 4 + 0] = v.x;
        Hs[r][kq * 4 + 1] = v.y;
        Hs[r][kq * 4 + 2] = v.z;
        Hs[r][kq * 4 + 3] = v.w;
    }

    const int tx = t & 15;   // col group (4 cols)
    const int ty = t >> 4;   // row group (4 rows)

    float acc[4][4] = {};

    for (int ko = 0; ko < 4; ko++) {
        __syncthreads();   // Hs ready (ko=0) / previous Ws consumers done
        #pragma unroll
        for (int j = 0; j < 2; j++) {
            int idx = t + j * 256;     // 0..511 float4
            ((float4*)Ws)[idx] = ((const float4*)(W + ko * 32 * DOUT))[idx];
        }
        __syncthreads();

        #pragma unroll
        for (int ki = 0; ki < 32; ki++) {
            float4 bv = *(const float4*)&Ws[ki * DOUT + tx * 4];
            float a0 = Hs[ty * 4 + 0][ko * 32 + ki];
            float a1 = Hs[ty * 4 + 1][ko * 32 + ki];
            float a2 = Hs[ty * 4 + 2][ko * 32 + ki];
            float a3 = Hs[ty * 4 + 3][ko * 32 + ki];
            acc[0][0] += a0 * bv.x; acc[0][1] += a0 * bv.y; acc[0][2] += a0 * bv.z; acc[0][3] += a0 * bv.w;
            acc[1][0] += a1 * bv.x; acc[1][1] += a1 * bv.y; acc[1][2] += a1 * bv.z; acc[1][3] += a1 * bv.w;
            acc[2][0] += a2 * bv.x; acc[2][1] += a2 * bv.y; acc[2][2] += a2 * bv.z; acc[2][3] += a2 * bv.w;
            acc[3][0] += a3 * bv.x; acc[3][1] += a3 * bv.y; acc[3][2] += a3 * bv.z; acc[3][3] += a3 * bv.w;
        }
    }

    float* xh = g_x[head];
    const float* dego = g_deg[2 * head];
    #pragma unroll
    for (int r = 0; r < 4; r++) {
        int row = rowbase + ty * 4 + r;
        if (row < NN) {
            float s = rsqrtf(fmaxf(dego[row], 1.0f));
            float4 o = make_float4(acc[r][0] * s, acc[r][1] * s, acc[r][2] * s, acc[r][3] * s);
            *(float4*)&xh[row * DOUT + tx * 4] = o;
        }
    }
}

// ---------------------------------------------------------------------------
// SpMM scatter: 16 threads per edge, each moves one float4 (vectorized red)
// ---------------------------------------------------------------------------
__global__ void scatter_kernel(const int* __restrict__ src,
                               const int* __restrict__ dst, int head) {
    int tid = blockIdx.x * blockDim.x + threadIdx.x;
    int e = tid >> 4;
    if (e >= EE) return;
    int c = tid & 15;
    int s = __ldg(src + e);
    int d = __ldg(dst + e);
    const float4 v = *(const float4*)(g_x[head] + s * DOUT + c * 4);
    float* p = g_agg[head] + d * DOUT + c * 4;
    asm volatile("red.global.add.v4.f32 [%0], {%1,%2,%3,%4};"
                 :: "l"(p), "f"(v.x), "f"(v.y), "f"(v.z), "f"(v.w)
                 : "memory");
}

// ---------------------------------------------------------------------------
// out = mean_h relu(agg_h * rsqrt(max(deg_in_h,1)) + b_h)
// ---------------------------------------------------------------------------
__global__ void combine_kernel(const float* __restrict__ b0,
                               const float* __restrict__ b1,
                               const float* __restrict__ b2,
                               float* __restrict__ out) {
    int tid = blockIdx.x * blockDim.x + threadIdx.x;
    if (tid >= NN * 16) return;
    int n = tid >> 4;
    int c = tid & 15;
    float s0 = rsqrtf(fmaxf(g_deg[1][n], 1.0f));
    float s1 = rsqrtf(fmaxf(g_deg[3][n], 1.0f));
    float s2 = rsqrtf(fmaxf(g_deg[5][n], 1.0f));
    float4 a0 = *(const float4*)(g_agg[0] + n * DOUT + c * 4);
    float4 a1 = *(const float4*)(g_agg[1] + n * DOUT + c * 4);
    float4 a2 = *(const float4*)(g_agg[2] + n * DOUT + c * 4);
    float4 v0 = ((const float4*)b0)[c];
    float4 v1 = ((const float4*)b1)[c];
    float4 v2 = ((const float4*)b2)[c];
    const float third = 1.0f / 3.0f;
    float4 r;
    r.x = (fmaxf(a0.x * s0 + v0.x, 0.f) + fmaxf(a1.x * s1 + v1.x, 0.f) + fmaxf(a2.x * s2 + v2.x, 0.f)) * third;
    r.y = (fmaxf(a0.y * s0 + v0.y, 0.f) + fmaxf(a1.y * s1 + v1.y, 0.f) + fmaxf(a2.y * s2 + v2.y, 0.f)) * third;
    r.z = (fmaxf(a0.z * s0 + v0.z, 0.f) + fmaxf(a1.z * s1 + v1.z, 0.f) + fmaxf(a2.z * s2 + v2.z, 0.f)) * third;
    r.w = (fmaxf(a0.w * s0 + v0.w, 0.f) + fmaxf(a1.w * s1 + v1.w, 0.f) + fmaxf(a2.w * s2 + v2.w, 0.f)) * third;
    *(float4*)(out + n * DOUT + c * 4) = r;
}

// ---------------------------------------------------------------------------
// metadata.txt order (setup_inputs dict order):
//   0:h  1:src0 2:dst0 3:W0 4:b0  5:src1 6:dst1 7:W1 8:b1  9:src2 10:dst2 11:W2 12:b2
// ---------------------------------------------------------------------------
extern "C" void kernel_launch(void* const* d_in, const int* in_sizes, int n_in,
                              void* d_out, int out_size) {
    const float* h  = (const float*)d_in[0];
    const int*   s0 = (const int*)d_in[1];
    const int*   d0 = (const int*)d_in[2];
    const float* W0 = (const float*)d_in[3];
    const float* b0 = (const float*)d_in[4];
    const int*   s1 = (const int*)d_in[5];
    const int*   d1 = (const int*)d_in[6];
    const float* W1 = (const float*)d_in[7];
    const float* b1 = (const float*)d_in[8];
    const int*   s2 = (const int*)d_in[9];
    const int*   d2 = (const int*)d_in[10];
    const float* W2 = (const float*)d_in[11];
    const float* b2 = (const float*)d_in[12];
    float* out = (float*)d_out;

    void* degp = nullptr;
    void* aggp = nullptr;
    cudaGetSymbolAddress(&degp, g_deg);
    cudaGetSymbolAddress(&aggp, g_agg);
    cudaMemsetAsync(degp, 0, sizeof(float) * 6 * NN, 0);
    cudaMemsetAsync(aggp, 0, sizeof(float) * 3 * NN * DOUT, 0);

    deg_kernel<<<(EE + 255) / 256, 256>>>(s0, d0, s1, d1, s2, d2);

    dim3 gg((NN + 63) / 64, 3);
    gemm_kernel<<<gg, 256>>>(h, W0, W1, W2);

    const int sblocks = (EE * 16) / 256;   // 25.6M threads / 256 = 100000 exactly
    scatter_kernel<<<sblocks, 256>>>(s0, d0, 0);
    scatter_kernel<<<sblocks, 256>>>(s1, d1, 1);
    scatter_kernel<<<sblocks, 256>>>(s2, d2, 2);

    combine_kernel<<<(NN * 16 + 255) / 256, 256>>>(b0, b1, b2, out);
}

// round 5
// speedup vs baseline: 1.1572x; 1.1572x over previous
#include <cuda_runtime.h>

#define NN   50000
#define EE   1600000
#define DIN  128
#define DOUT 64

// Scratch (static device globals: allocation-free, allowed)
__device__ __align__(16) float g_x[3][NN * DOUT];  // (h @ W_h) * rsqrt(deg_out_h)
__device__ int g_hist[6][NN];                      // [0..2]=src hist (deg_out), [3..5]=dst hist
__device__ int g_off[3][NN + 1];                   // CSR row offsets (by dst)
__device__ int g_cur[3][NN];                       // placement cursors
__device__ int g_csr[3][EE];                       // src indices grouped by dst

// ---------------------------------------------------------------------------
// Integer degree histograms for all 3 heads (src & dst)
// ---------------------------------------------------------------------------
__global__ void hist_kernel(const int* __restrict__ s0, const int* __restrict__ d0,
                            const int* __restrict__ s1, const int* __restrict__ d1,
                            const int* __restrict__ s2, const int* __restrict__ d2) {
    int i = blockIdx.x * blockDim.x + threadIdx.x;
    if (i >= EE) return;
    atomicAdd(&g_hist[0][s0[i]], 1);
    atomicAdd(&g_hist[3][d0[i]], 1);
    atomicAdd(&g_hist[1][s1[i]], 1);
    atomicAdd(&g_hist[4][d1[i]], 1);
    atomicAdd(&g_hist[2][s2[i]], 1);
    atomicAdd(&g_hist[5][d2[i]], 1);
}

// ---------------------------------------------------------------------------
// Exclusive scan of dst histogram -> CSR offsets + cursors. One block per head.
// ---------------------------------------------------------------------------
__global__ void scan_kernel() {
    const int h = blockIdx.x;
    const int CH = (NN + 1023) / 1024;   // 49
    const int t = threadIdx.x;
    int beg = t * CH;
    int end = min(beg + CH, NN);

    int sum = 0;
    for (int i = beg; i < end; i++) sum += g_hist[3 + h][i];

    __shared__ int ps[1024];
    ps[t] = sum;
    __syncthreads();
    for (int ofs = 1; ofs < 1024; ofs <<= 1) {
        int v = 0;
        if (t >= ofs) v = ps[t - ofs];
        __syncthreads();
        if (t >= ofs) ps[t] += v;
        __syncthreads();
    }

    int prefix = (t == 0) ? 0 : ps[t - 1];
    for (int i = beg; i < end; i++) {
        g_off[h][i] = prefix;
        g_cur[h][i] = prefix;
        prefix += g_hist[3 + h][i];
    }
    if (t == 1023) g_off[h][NN] = prefix;   // == EE
}

// ---------------------------------------------------------------------------
// CSR placement: csr[pos] = src, grouped by dst
// ---------------------------------------------------------------------------
__global__ void place_kernel(const int* __restrict__ s0, const int* __restrict__ d0,
                             const int* __restrict__ s1, const int* __restrict__ d1,
                             const int* __restrict__ s2, const int* __restrict__ d2) {
    const int h = blockIdx.y;
    const int* s = (h == 0) ? s0 : (h == 1) ? s1 : s2;
    const int* d = (h == 0) ? d0 : (h == 1) ? d1 : d2;
    int e = blockIdx.x * blockDim.x + threadIdx.x;
    if (e >= EE) return;
    int dd = d[e];
    int pos = atomicAdd(&g_cur[h][dd], 1);
    g_csr[h][pos] = s[e];
}

// ---------------------------------------------------------------------------
// Fused 3-head GEMM: x_h = (h @ W_h) * rsqrt(max(deg_out_h,1))
// 256 threads, 64-row tile, all 3 heads share one H tile. K tiled by 16.
// smem: Hs 33.3KB + Ws 12KB = 45.5KB (under 48KB static limit).
// ---------------------------------------------------------------------------
__global__ void gemm_kernel(const float* __restrict__ h,
                            const float* __restrict__ W0,
                            const float* __restrict__ W1,
                            const float* __restrict__ W2) {
    __shared__ float Hs[64][130];
    __shared__ float Ws[3][16 * DOUT];

    const int t = threadIdx.x;
    const int rowbase = blockIdx.x * 64;

    // Load H tile (64 rows x 128 cols), zero-padded past N
    #pragma unroll
    for (int j = 0; j < 8; j++) {
        int idx = t + j * 256;
        int r = idx >> 5;
        int kq = idx & 31;
        int row = rowbase + r;
        float4 v = make_float4(0.f, 0.f, 0.f, 0.f);
        if (row < NN) v = ((const float4*)(h + (size_t)row * DIN))[kq];
        Hs[r][kq * 4 + 0] = v.x;
        Hs[r][kq * 4 + 1] = v.y;
        Hs[r][kq * 4 + 2] = v.z;
        Hs[r][kq * 4 + 3] = v.w;
    }

    const int tx = t & 15;
    const int ty = t >> 4;

    float acc[3][4][4] = {};

    for (int ko = 0; ko < 8; ko++) {
        __syncthreads();
        // each thread loads one float4 per head (16*64 floats = 256 float4 per head)
        ((float4*)Ws[0])[t] = ((const float4*)(W0 + ko * 16 * DOUT))[t];
        ((float4*)Ws[1])[t] = ((const float4*)(W1 + ko * 16 * DOUT))[t];
        ((float4*)Ws[2])[t] = ((const float4*)(W2 + ko * 16 * DOUT))[t];
        __syncthreads();

        #pragma unroll
        for (int ki = 0; ki < 16; ki++) {
            float a[4];
            #pragma unroll
            for (int r = 0; r < 4; r++) a[r] = Hs[ty * 4 + r][ko * 16 + ki];
            #pragma unroll
            for (int hh = 0; hh < 3; hh++) {
                float4 bv = *(const float4*)&Ws[hh][ki * DOUT + tx * 4];
                #pragma unroll
                for (int r = 0; r < 4; r++) {
                    acc[hh][r][0] += a[r] * bv.x;
                    acc[hh][r][1] += a[r] * bv.y;
                    acc[hh][r][2] += a[r] * bv.z;
                    acc[hh][r][3] += a[r] * bv.w;
                }
            }
        }
    }

    #pragma unroll
    for (int hh = 0; hh < 3; hh++) {
        float* xh = g_x[hh];
        #pragma unroll
        for (int r = 0; r < 4; r++) {
            int row = rowbase + ty * 4 + r;
            if (row < NN) {
                float s = rsqrtf(fmaxf((float)g_hist[hh][row], 1.0f));
                float4 o = make_float4(acc[hh][r][0] * s, acc[hh][r][1] * s,
                                       acc[hh][r][2] * s, acc[hh][r][3] * s);
                *(float4*)&xh[row * DOUT + tx * 4] = o;
            }
        }
    }
}

// ---------------------------------------------------------------------------
// Pull SpMM fused with epilogue: warp per dst node, loops over 3 heads.
// out[n] = mean_h relu( (sum_{e: dst=n} x_h[src_e]) * rsqrt(max(deg_in,1)) + b_h )
// ---------------------------------------------------------------------------
__global__ void pull_kernel(const float* __restrict__ b0,
                            const float* __restrict__ b1,
                            const float* __restrict__ b2,
                            float* __restrict__ out) {
    int n = (blockIdx.x * blockDim.x + threadIdx.x) >> 5;
    if (n >= NN) return;
    const int lane = threadIdx.x & 31;

    float rx = 0.f, ry = 0.f;

    #pragma unroll
    for (int h = 0; h < 3; h++) {
        const float* xh = g_x[h];
        const int* csr = g_csr[h];
        const int beg = g_off[h][n];
        const int end = g_off[h][n + 1];

        float ax = 0.f, ay = 0.f;
        int i = beg;
        for (; i + 4 <= end; i += 4) {
            int s0 = csr[i], s1 = csr[i + 1], s2 = csr[i + 2], s3 = csr[i + 3];
            float2 v0 = *(const float2*)(xh + s0 * DOUT + lane * 2);
            float2 v1 = *(const float2*)(xh + s1 * DOUT + lane * 2);
            float2 v2 = *(const float2*)(xh + s2 * DOUT + lane * 2);
            float2 v3 = *(const float2*)(xh + s3 * DOUT + lane * 2);
            ax += (v0.x + v1.x) + (v2.x + v3.x);
            ay += (v0.y + v1.y) + (v2.y + v3.y);
        }
        for (; i < end; i++) {
            int s = csr[i];
            float2 v = *(const float2*)(xh + s * DOUT + lane * 2);
            ax += v.x;
            ay += v.y;
        }

        float scale = rsqrtf(fmaxf((float)(end - beg), 1.0f));
        const float* bb = (h == 0) ? b0 : (h == 1) ? b1 : b2;
        rx += fmaxf(ax * scale + bb[lane * 2 + 0], 0.f);
        ry += fmaxf(ay * scale + bb[lane * 2 + 1], 0.f);
    }

    const float third = 1.0f / 3.0f;
    float2 o = make_float2(rx * third, ry * third);
    *(float2*)(out + n * DOUT + lane * 2) = o;
}

// ---------------------------------------------------------------------------
// metadata.txt order:
//   0:h  1:src0 2:dst0 3:W0 4:b0  5:src1 6:dst1 7:W1 8:b1  9:src2 10:dst2 11:W2 12:b2
// ---------------------------------------------------------------------------
extern "C" void kernel_launch(void* const* d_in, const int* in_sizes, int n_in,
                              void* d_out, int out_size) {
    const float* h  = (const float*)d_in[0];
    const int*   s0 = (const int*)d_in[1];
    const int*   d0 = (const int*)d_in[2];
    const float* W0 = (const float*)d_in[3];
    const float* b0 = (const float*)d_in[4];
    const int*   s1 = (const int*)d_in[5];
    const int*   d1 = (const int*)d_in[6];
    const float* W1 = (const float*)d_in[7];
    const float* b1 = (const float*)d_in[8];
    const int*   s2 = (const int*)d_in[9];
    const int*   d2 = (const int*)d_in[10];
    const float* W2 = (const float*)d_in[11];
    const float* b2 = (const float*)d_in[12];
    float* out = (float*)d_out;

    void* histp = nullptr;
    cudaGetSymbolAddress(&histp, g_hist);
    cudaMemsetAsync(histp, 0, sizeof(int) * 6 * NN, 0);

    const int eblocks = (EE + 255) / 256;   // 6250

    hist_kernel<<<eblocks, 256>>>(s0, d0, s1, d1, s2, d2);
    scan_kernel<<<3, 1024>>>();
    place_kernel<<<dim3(eblocks, 3), 256>>>(s0, d0, s1, d1, s2, d2);

    gemm_kernel<<<(NN + 63) / 64, 256>>>(h, W0, W1, W2);

    pull_kernel<<<(NN * 32 + 255) / 256, 256>>>(b0, b1, b2, out);
}